// round 1
// baseline (speedup 1.0000x reference)
#include <cuda_runtime.h>

// 5x5 bilateral filter, fp32, reflect padding, [B=4, C=3, H=512, W=512].
// One pixel per thread; 32x8 block with a (32+4)x(8+4) shared tile.

#define KSZ 5
#define PAD 2
#define TX 32
#define TY 8
#define SW (TX + 2 * PAD)   // 36
#define SH (TY + 2 * PAD)   // 12

__global__ __launch_bounds__(TX * TY)
void bilateral_kernel(const float* __restrict__ x,
                      const float* __restrict__ sk,
                      const float* __restrict__ sigma_color_p,
                      float* __restrict__ out,
                      int H, int W)
{
    __shared__ float tile[SH][SW];
    __shared__ float sks[KSZ * KSZ];

    const int tx = threadIdx.x;
    const int ty = threadIdx.y;
    const int tid = ty * TX + tx;
    const int bx = blockIdx.x * TX;
    const int by = blockIdx.y * TY;

    const float* __restrict__ xc = x + (size_t)blockIdx.z * H * W;

    if (tid < KSZ * KSZ) sks[tid] = sk[tid];

    // Cooperative tile load with reflect padding (mirror, no edge repeat).
    #pragma unroll
    for (int i = tid; i < SH * SW; i += TX * TY) {
        int sy = i / SW;
        int sx = i - sy * SW;
        int gy = by + sy - PAD;
        int gx = bx + sx - PAD;
        gy = (gy < 0) ? -gy : ((gy >= H) ? (2 * H - 2 - gy) : gy);
        gx = (gx < 0) ? -gx : ((gx >= W) ? (2 * W - 2 - gx) : gx);
        tile[sy][sx] = xc[gy * W + gx];
    }
    __syncthreads();

    const float sigma = *sigma_color_p;
    // exp(-(d^2)/(2 sigma^2)) == exp2(d^2 * negK)
    const float negK = -1.4426950408889634f / (2.0f * sigma * sigma);

    const float c = tile[ty + PAD][tx + PAD];
    float wsum = 0.0f;
    float acc = 0.0f;

    #pragma unroll
    for (int i = 0; i < KSZ; i++) {
        #pragma unroll
        for (int j = 0; j < KSZ; j++) {
            float p = tile[ty + i][tx + j];
            float d = p - c;
            float arg = d * d * negK;
            float e;
            asm("ex2.approx.f32 %0, %1;" : "=f"(e) : "f"(arg));
            float w = sks[i * KSZ + j] * e;
            wsum += w;
            acc = fmaf(w, p, acc);
        }
    }

    out[(size_t)blockIdx.z * H * W + (size_t)(by + ty) * W + (bx + tx)] =
        acc / (wsum + 1e-8f);
}

extern "C" void kernel_launch(void* const* d_in, const int* in_sizes, int n_in,
                              void* d_out, int out_size)
{
    const float* x  = (const float*)d_in[0];
    const float* sk = (const float*)d_in[1];
    const float* sc = (const float*)d_in[2];
    float* out = (float*)d_out;

    const int H = 512, W = 512;
    const int channels = in_sizes[0] / (H * W);  // B*C = 12

    dim3 block(TX, TY, 1);
    dim3 grid(W / TX, H / TY, channels);
    bilateral_kernel<<<grid, block>>>(x, sk, sc, out, H, W);
}